// round 8
// baseline (speedup 1.0000x reference)
#include <cuda_runtime.h>
#include <cuda_fp16.h>
#include <cstdint>

// Problem constants
#define B_  4
#define L_  4096
#define H_  1024
#define U_  1024
#define M_  (B_*L_)          // 16384 rows

constexpr int CL = 64;            // scan chunk length
constexpr int NC = L_ / CL;       // 64 chunks per sequence

// ---------------- scratch (device globals; no allocation allowed) -------------
__device__ __half g_inH[(size_t)M_ * H_];   // fp16 inputs          (32 MB)
__device__ __half g_WiH[(size_t)U_ * H_];   // fp16 Wi              (2 MB)
__device__ __half g_WoH[(size_t)H_ * U_];   // fp16 Wo              (2 MB)
__device__ __half g_uh [(size_t)M_ * U_];   // fp16 scanned x       (32 MB)
__device__ float  g_u  [(size_t)M_ * U_];   // fp32 u (pre-scan)    (64 MB)
__device__ float  g_v  [(size_t)B_ * NC * U_]; // chunk carries      (1 MB)

// ---------------- helpers ----------------------------------------------------
__device__ __forceinline__ uint32_t smem_u32(const void* p) {
    uint32_t a;
    asm("{ .reg .u64 t; cvta.to.shared.u64 t, %1; cvt.u32.u64 %0, t; }"
        : "=r"(a) : "l"(p));
    return a;
}

__device__ __forceinline__ void cp16(uint32_t saddr, const void* g) {
    asm volatile("cp.async.cg.shared.global [%0], [%1], 16;" :: "r"(saddr), "l"(g));
}
__device__ __forceinline__ void cp_commit() {
    asm volatile("cp.async.commit_group;" ::: "memory");
}

// ldmatrix x4: 4 matrices of 8 rows x 16B (8 halves).
__device__ __forceinline__ void ldsm4(uint32_t* r, uint32_t addr) {
    asm volatile("ldmatrix.sync.aligned.m8n8.x4.shared.b16 {%0,%1,%2,%3}, [%4];"
                 : "=r"(r[0]), "=r"(r[1]), "=r"(r[2]), "=r"(r[3]) : "r"(addr));
}

__device__ __forceinline__ void mma_f16(float* d, const uint32_t* a, const uint32_t* b) {
    asm volatile(
        "mma.sync.aligned.m16n8k16.row.col.f32.f16.f16.f32 "
        "{%0,%1,%2,%3}, {%4,%5,%6,%7}, {%8,%9}, {%0,%1,%2,%3};\n"
        : "+f"(d[0]), "+f"(d[1]), "+f"(d[2]), "+f"(d[3])
        : "r"(a[0]), "r"(a[1]), "r"(a[2]), "r"(a[3]),
          "r"(b[0]), "r"(b[1]));
}

// ---------------- fp16 conversion pass ---------------------------------------
__global__ void cvt_f16_kernel(int sel, const float4* __restrict__ src) {
    __half* dst;
    size_t n8;
    if (sel == 0)      { dst = g_inH; n8 = (size_t)M_ * H_ / 8; }
    else if (sel == 1) { dst = g_WiH; n8 = (size_t)U_ * H_ / 8; }
    else               { dst = g_WoH; n8 = (size_t)H_ * U_ / 8; }
    size_t i = (size_t)blockIdx.x * blockDim.x + threadIdx.x;
    size_t stride = (size_t)gridDim.x * blockDim.x;
    for (; i < n8; i += stride) {
        float4 a = src[2 * i], b = src[2 * i + 1];
        __half2 h[4];
        h[0] = __floats2half2_rn(a.x, a.y);
        h[1] = __floats2half2_rn(a.z, a.w);
        h[2] = __floats2half2_rn(b.x, b.y);
        h[3] = __floats2half2_rn(b.z, b.w);
        reinterpret_cast<uint4*>(dst)[i] = *reinterpret_cast<uint4*>(h);
    }
}

// ---------------- FP16 mma GEMM: C = A*B^T + bias ----------------------------
// CTA 128x128, 4 warps (2x2), warp tile 64x64, BK=64 halves (=128B rows),
// 3-stage cp.async, mma m16n8k16, fp32 accum. 2 CTAs/SM.
constexpr int TM = 128, TN = 128, BKH = 64;   // BKH in halves
constexpr int KDIM = 1024;                    // halves
constexpr int NKT  = KDIM / BKH;              // 16 chunks
constexpr int NSTAGE = 3;
constexpr int STAGE_A   = TM * 128;           // 16384 B per operand tile
constexpr int STAGE_TOT = 2 * STAGE_A;        // 32768 B
constexpr int GEMM_SMEM = NSTAGE * STAGE_TOT; // 98304 B

__global__ __launch_bounds__(128, 2)
void gemm_f16_kernel(int sel, const float* __restrict__ bias, float* __restrict__ Cext)
{
    extern __shared__ char smem[];
    const uint32_t sb = smem_u32(smem);
    const int tid = threadIdx.x;
    const int warp = tid >> 5, lane = tid & 31;

    const __half* __restrict__ A  = sel ? g_uh  : g_inH;
    const __half* __restrict__ Bw = sel ? g_WoH : g_WiH;
    float* __restrict__ C         = sel ? Cext  : g_u;
    const int bm = blockIdx.y * TM;
    const int bn = blockIdx.x * TN;

    const int wm = (warp >> 1) * 64;      // warp M offset (0/64)
    const int wn = (warp & 1) * 64;       // warp N offset (0/64)

    // ---- staging: one thread = one 128B row; 8 chunks of 16B each ----
    const int srow = tid;                 // 0..127
    uint32_t swoff[8];
    #pragma unroll
    for (int i = 0; i < 8; i++)
        swoff[i] = (uint32_t)srow * 128u + ((uint32_t)(i ^ (srow & 7)) << 4);
    const __half* Arow = A  + (size_t)(bm + srow) * KDIM;
    const __half* Brow = Bw + (size_t)(bn + srow) * KDIM;

    // ---- ldmatrix per-lane invariants (x4, non-trans) ----
    const int lrA  = lane & 15;           // A row-in-16
    const int gsA  = lane >> 4;           // A k-chunk select (0/1)
    const int lrB  = ((lane & 16) >> 1) + (lane & 7);   // B row offset 0..15
    const int gsB  = (lane >> 3) & 1;     // B k-chunk select

    float acc[4][8][4];
    #pragma unroll
    for (int mt = 0; mt < 4; mt++)
        #pragma unroll
        for (int nt = 0; nt < 8; nt++)
            #pragma unroll
            for (int i = 0; i < 4; i++) acc[mt][nt][i] = 0.f;

    // ---- prologue: stage chunks 0,1 ----
    #pragma unroll
    for (int c = 0; c < NSTAGE - 1; c++) {
        const uint32_t ao = sb + c * STAGE_TOT;
        #pragma unroll
        for (int i = 0; i < 8; i++) {
            cp16(ao + swoff[i], Arow + c * BKH + i * 8);
            cp16(ao + STAGE_A + swoff[i], Brow + c * BKH + i * 8);
        }
        cp_commit();
    }

    #pragma unroll 1
    for (int kt = 0; kt < NKT; kt++) {
        asm volatile("cp.async.wait_group 1;" ::: "memory");
        __syncthreads();

        if (kt + 2 < NKT) {
            const uint32_t ao = sb + ((kt + 2) % NSTAGE) * STAGE_TOT;
            const int k0 = (kt + 2) * BKH;
            #pragma unroll
            for (int i = 0; i < 8; i++) {
                cp16(ao + swoff[i], Arow + k0 + i * 8);
                cp16(ao + STAGE_A + swoff[i], Brow + k0 + i * 8);
            }
        }
        cp_commit();

        const uint32_t sA = sb + (kt % NSTAGE) * STAGE_TOT;
        const uint32_t sB = sA + STAGE_A;

        #pragma unroll
        for (int ks = 0; ks < 4; ks++) {          // 4 x k16 per 64-half chunk
            uint32_t afr[4][4], bfr[4][4];
            #pragma unroll
            for (int mt = 0; mt < 4; mt++) {
                const int r = wm + mt * 16 + lrA;
                const uint32_t g = (uint32_t)((ks * 2 + gsA) ^ (lrA & 7));
                ldsm4(afr[mt], sA + (uint32_t)r * 128u + (g << 4));
            }
            #pragma unroll
            for (int p = 0; p < 4; p++) {
                const int r = wn + p * 16 + lrB;
                const uint32_t g = (uint32_t)((ks * 2 + gsB) ^ (lrB & 7));
                ldsm4(bfr[p], sB + (uint32_t)r * 128u + (g << 4));
            }
            #pragma unroll
            for (int mt = 0; mt < 4; mt++)
                #pragma unroll
                for (int nt = 0; nt < 8; nt++)
                    mma_f16(acc[mt][nt], afr[mt], &bfr[nt >> 1][(nt & 1) * 2]);
        }
    }

    // ---- epilogue: add bias, write fp32 ----
    const int gid = lane >> 2, t4 = lane & 3;
    #pragma unroll
    for (int mt = 0; mt < 4; mt++) {
        const int row = bm + wm + mt * 16 + gid;
        #pragma unroll
        for (int nt = 0; nt < 8; nt++) {
            const int col = bn + wn + nt * 8 + t4 * 2;
            const float b0 = bias[col], b1 = bias[col + 1];
            float2 v0 = make_float2(acc[mt][nt][0] + b0, acc[mt][nt][1] + b1);
            float2 v1 = make_float2(acc[mt][nt][2] + b0, acc[mt][nt][3] + b1);
            *reinterpret_cast<float2*>(&C[(size_t)row * 1024 + col]) = v0;
            *reinterpret_cast<float2*>(&C[(size_t)(row + 8) * 1024 + col]) = v1;
        }
    }
}

// ---------------- scan: h_t = lam*h_{t-1} + u_t, chunked (fp32) ---------------
// K1: chunk aggregates only -> g_v
__global__ void scan_agg_kernel(const float* __restrict__ plog)
{
    const int g  = blockIdx.x * 256 + threadIdx.x;   // B*NC*U threads
    const int uu = g & (U_ - 1);
    const int c  = (g >> 10) & (NC - 1);
    const int b  = g >> 16;
    const float lam = expf(-expf(plog[uu]));
    const float* p = g_u + (size_t)(b * L_ + c * CL) * U_ + uu;
    float h = 0.f;
    #pragma unroll 8
    for (int t = 0; t < CL; t++)
        h = fmaf(lam, h, p[(size_t)t * U_]);
    g_v[(size_t)(b * NC + c) * U_ + uu] = h;
}

// K2: exclusive scan of chunk aggregates along the chunk axis (per b,u).
__global__ void scan_carry_kernel(const float* __restrict__ plog)
{
    const int g  = blockIdx.x * 256 + threadIdx.x;   // B*U threads
    const int uu = g & (U_ - 1);
    const int b  = g >> 10;
    const float nu   = expf(plog[uu]);
    const float lamC = expf(-(float)CL * nu);
    float* p = g_v + (size_t)b * NC * U_ + uu;
    float carry = 0.f;
    #pragma unroll 1
    for (int c = 0; c < NC; c++) {
        float t = p[(size_t)c * U_];
        p[(size_t)c * U_] = carry;           // exclusive (state at chunk start)
        carry = fmaf(lamC, carry, t);
    }
}

// K3: redo local scan seeded with carry, * gamma, emit fp16 operand for GEMM2.
__global__ void scan_apply_kernel(const float* __restrict__ plog)
{
    const int g  = blockIdx.x * 256 + threadIdx.x;   // B*NC*U threads
    const int uu = g & (U_ - 1);
    const int c  = (g >> 10) & (NC - 1);
    const int b  = g >> 16;
    const float lam = expf(-expf(plog[uu]));
    const float gam = expf(plog[U_ + uu]);
    float h = g_v[(size_t)(b * NC + c) * U_ + uu];   // state before chunk
    const float* p = g_u + (size_t)(b * L_ + c * CL) * U_ + uu;
    __half*      q = g_uh + (size_t)(b * L_ + c * CL) * U_ + uu;
    #pragma unroll 8
    for (int t = 0; t < CL; t++) {
        h = fmaf(lam, h, p[(size_t)t * U_]);
        q[(size_t)t * U_] = __float2half_rn(h * gam);
    }
}

// ---------------- launch ------------------------------------------------------
extern "C" void kernel_launch(void* const* d_in, const int* in_sizes, int n_in,
                              void* d_out, int out_size)
{
    const float* inputs = (const float*)d_in[0];
    const float* Wi     = (const float*)d_in[1];
    const float* bi     = (const float*)d_in[2];
    const float* Wo     = (const float*)d_in[3];
    const float* bo     = (const float*)d_in[4];
    const float* plog   = (const float*)d_in[5];
    float* out = (float*)d_out;

    cudaFuncSetAttribute(gemm_f16_kernel,
                         cudaFuncAttributeMaxDynamicSharedMemorySize,
                         GEMM_SMEM);

    // fp16 conversion (off the GEMM critical path)
    cvt_f16_kernel<<<2048, 256>>>(0, (const float4*)inputs);
    cvt_f16_kernel<<<256, 256>>>(1, (const float4*)Wi);
    cvt_f16_kernel<<<256, 256>>>(2, (const float4*)Wo);

    // GEMM1: u = inputs * Wi^T + bi   -> g_u (fp32)
    gemm_f16_kernel<<<dim3(U_ / TN, M_ / TM), 128, GEMM_SMEM>>>(0, bi, nullptr);

    // scan (chunked linear recurrence) + gamma -> g_uh (fp16)
    scan_agg_kernel<<<(B_ * NC * U_) / 256, 256>>>(plog);
    scan_carry_kernel<<<(B_ * U_) / 256, 256>>>(plog);
    scan_apply_kernel<<<(B_ * NC * U_) / 256, 256>>>(plog);

    // GEMM2: out = x * Wo^T + bo
    gemm_f16_kernel<<<dim3(H_ / TN, M_ / TM), 128, GEMM_SMEM>>>(1, bo, out);
}

// round 9
// speedup vs baseline: 1.4298x; 1.4298x over previous
#include <cuda_runtime.h>
#include <cuda_fp16.h>
#include <cstdint>

// Problem constants
#define B_  4
#define L_  4096
#define H_  1024
#define U_  1024
#define M_  (B_*L_)          // 16384 rows

constexpr int CL = 64;            // scan chunk length
constexpr int NC = L_ / CL;       // 64 chunks per sequence

// ---------------- scratch (device globals; no allocation allowed) -------------
__device__ __half g_inH[(size_t)M_ * H_];   // fp16 inputs          (32 MB)
__device__ __half g_WiH[(size_t)U_ * H_];   // fp16 Wi              (2 MB)
__device__ __half g_WoH[(size_t)H_ * U_];   // fp16 Wo              (2 MB)
__device__ __half g_uh [(size_t)M_ * U_];   // fp16 scanned x       (32 MB)
__device__ float  g_u  [(size_t)M_ * U_];   // fp32 u (pre-scan)    (64 MB)
__device__ float  g_v  [(size_t)B_ * NC * U_]; // chunk carries      (1 MB)

// ---------------- helpers ----------------------------------------------------
__device__ __forceinline__ uint32_t smem_u32(const void* p) {
    uint32_t a;
    asm("{ .reg .u64 t; cvta.to.shared.u64 t, %1; cvt.u32.u64 %0, t; }"
        : "=r"(a) : "l"(p));
    return a;
}

__device__ __forceinline__ void cp16(uint32_t saddr, const void* g) {
    asm volatile("cp.async.cg.shared.global [%0], [%1], 16;" :: "r"(saddr), "l"(g));
}
__device__ __forceinline__ void cp_commit() {
    asm volatile("cp.async.commit_group;" ::: "memory");
}

// ldmatrix x4: 4 matrices of 8 rows x 16B (8 halves).
__device__ __forceinline__ void ldsm4(uint32_t* r, uint32_t addr) {
    asm volatile("ldmatrix.sync.aligned.m8n8.x4.shared.b16 {%0,%1,%2,%3}, [%4];"
                 : "=r"(r[0]), "=r"(r[1]), "=r"(r[2]), "=r"(r[3]) : "r"(addr));
}

__device__ __forceinline__ void mma_f16(float* d, const uint32_t* a, const uint32_t* b) {
    asm volatile(
        "mma.sync.aligned.m16n8k16.row.col.f32.f16.f16.f32 "
        "{%0,%1,%2,%3}, {%4,%5,%6,%7}, {%8,%9}, {%0,%1,%2,%3};\n"
        : "+f"(d[0]), "+f"(d[1]), "+f"(d[2]), "+f"(d[3])
        : "r"(a[0]), "r"(a[1]), "r"(a[2]), "r"(a[3]),
          "r"(b[0]), "r"(b[1]));
}

// ---------------- fused fp16 conversion (inputs + Wi + Wo) --------------------
__global__ void cvt_all_kernel(const float4* __restrict__ in,
                               const float4* __restrict__ wi,
                               const float4* __restrict__ wo)
{
    const size_t n_in = (size_t)M_ * H_ / 8;    // uint4 (8-half) chunks
    const size_t n_w  = (size_t)U_ * H_ / 8;
    const size_t n_tot = n_in + 2 * n_w;
    size_t i = (size_t)blockIdx.x * blockDim.x + threadIdx.x;
    const size_t stride = (size_t)gridDim.x * blockDim.x;
    for (; i < n_tot; i += stride) {
        const float4* src;
        __half* dst;
        size_t j;
        if (i < n_in)            { src = in; dst = g_inH; j = i; }
        else if (i < n_in + n_w) { src = wi; dst = g_WiH; j = i - n_in; }
        else                     { src = wo; dst = g_WoH; j = i - n_in - n_w; }
        float4 a = src[2 * j], b = src[2 * j + 1];
        __half2 h[4];
        h[0] = __floats2half2_rn(a.x, a.y);
        h[1] = __floats2half2_rn(a.z, a.w);
        h[2] = __floats2half2_rn(b.x, b.y);
        h[3] = __floats2half2_rn(b.z, b.w);
        reinterpret_cast<uint4*>(dst)[j] = *reinterpret_cast<uint4*>(h);
    }
}

// ---------------- FP16 mma GEMM: C = A*B^T + bias (R7 config) ----------------
// CTA 128x128, 8 warps (4M x 2N), warp tile 32x64, BK=64 halves (=128B rows),
// 3-stage cp.async, mma m16n8k16, fp32 accum. 2 CTAs/SM.
constexpr int TM = 128, TN = 128, BKH = 64;   // BKH in halves
constexpr int KDIM = 1024;                    // halves
constexpr int NKT  = KDIM / BKH;              // 16 chunks
constexpr int NSTAGE = 3;
constexpr int STAGE_A   = TM * 128;           // 16384 B per operand tile
constexpr int STAGE_TOT = 2 * STAGE_A;        // 32768 B
constexpr int GEMM_SMEM = NSTAGE * STAGE_TOT; // 98304 B

__global__ __launch_bounds__(256, 2)
void gemm_f16_kernel(int sel, const float* __restrict__ bias, float* __restrict__ Cext)
{
    extern __shared__ char smem[];
    const uint32_t sb = smem_u32(smem);
    const int tid = threadIdx.x;
    const int warp = tid >> 5, lane = tid & 31;

    const __half* __restrict__ A  = sel ? g_uh  : g_inH;
    const __half* __restrict__ Bw = sel ? g_WoH : g_WiH;
    float* __restrict__ C         = sel ? Cext  : g_u;
    const int bm = blockIdx.y * TM;
    const int bn = blockIdx.x * TN;

    const int wm = (warp >> 1) * 32;      // warp M offset
    const int wn = (warp & 1) * 64;       // warp N offset

    // ---- staging: thread -> (row, 16B-chunk group); rows are 128B ----
    const int srow = tid >> 1;            // 0..127
    const int gb0  = (tid & 1) * 4;       // chunk base 0 or 4
    uint32_t swoff[4];
    #pragma unroll
    for (int i = 0; i < 4; i++)
        swoff[i] = (uint32_t)srow * 128u + ((uint32_t)((gb0 + i) ^ (srow & 7)) << 4);
    const __half* Arow = A  + (size_t)(bm + srow) * KDIM;
    const __half* Brow = Bw + (size_t)(bn + srow) * KDIM;

    // ---- ldmatrix per-lane invariants (A x4 and B x4, non-trans) ----
    const int lrA  = lane & 15;           // A row-in-16
    const int gsA  = lane >> 4;           // A k-chunk select (0/1)
    const int lrB  = ((lane & 16) >> 1) + (lane & 7);   // B row offset 0..15
    const int gsB  = (lane >> 3) & 1;     // B k-chunk select

    float acc[2][8][4];
    #pragma unroll
    for (int mt = 0; mt < 2; mt++)
        #pragma unroll
        for (int nt = 0; nt < 8; nt++)
            #pragma unroll
            for (int i = 0; i < 4; i++) acc[mt][nt][i] = 0.f;

    // ---- prologue: stage chunks 0,1 ----
    #pragma unroll
    for (int c = 0; c < NSTAGE - 1; c++) {
        const uint32_t ao = sb + c * STAGE_TOT;
        #pragma unroll
        for (int i = 0; i < 4; i++) {
            cp16(ao + swoff[i], Arow + c * BKH + (gb0 + i) * 8);
            cp16(ao + STAGE_A + swoff[i], Brow + c * BKH + (gb0 + i) * 8);
        }
        cp_commit();
    }

    #pragma unroll 1
    for (int kt = 0; kt < NKT; kt++) {
        asm volatile("cp.async.wait_group 1;" ::: "memory");
        __syncthreads();

        if (kt + 2 < NKT) {
            const uint32_t ao = sb + ((kt + 2) % NSTAGE) * STAGE_TOT;
            const int k0 = (kt + 2) * BKH;
            #pragma unroll
            for (int i = 0; i < 4; i++) {
                cp16(ao + swoff[i], Arow + k0 + (gb0 + i) * 8);
                cp16(ao + STAGE_A + swoff[i], Brow + k0 + (gb0 + i) * 8);
            }
        }
        cp_commit();

        const uint32_t sA = sb + (kt % NSTAGE) * STAGE_TOT;
        const uint32_t sB = sA + STAGE_A;

        #pragma unroll
        for (int ks = 0; ks < 4; ks++) {          // 4 x k16 per 64-half chunk
            uint32_t afr[2][4], bfr[4][4];
            #pragma unroll
            for (int mt = 0; mt < 2; mt++) {
                const int r = wm + mt * 16 + lrA;
                const uint32_t g = (uint32_t)((ks * 2 + gsA) ^ (lrA & 7));
                ldsm4(afr[mt], sA + (uint32_t)r * 128u + (g << 4));
            }
            #pragma unroll
            for (int p = 0; p < 4; p++) {
                const int r = wn + p * 16 + lrB;
                const uint32_t g = (uint32_t)((ks * 2 + gsB) ^ (lrB & 7));
                ldsm4(bfr[p], sB + (uint32_t)r * 128u + (g << 4));
            }
            #pragma unroll
            for (int mt = 0; mt < 2; mt++)
                #pragma unroll
                for (int nt = 0; nt < 8; nt++)
                    mma_f16(acc[mt][nt], afr[mt], &bfr[nt >> 1][(nt & 1) * 2]);
        }
    }

    // ---- epilogue: add bias, write fp32 ----
    const int gid = lane >> 2, t4 = lane & 3;
    #pragma unroll
    for (int mt = 0; mt < 2; mt++) {
        const int row = bm + wm + mt * 16 + gid;
        #pragma unroll
        for (int nt = 0; nt < 8; nt++) {
            const int col = bn + wn + nt * 8 + t4 * 2;
            const float b0 = bias[col], b1 = bias[col + 1];
            float2 v0 = make_float2(acc[mt][nt][0] + b0, acc[mt][nt][1] + b1);
            float2 v1 = make_float2(acc[mt][nt][2] + b0, acc[mt][nt][3] + b1);
            *reinterpret_cast<float2*>(&C[(size_t)row * 1024 + col]) = v0;
            *reinterpret_cast<float2*>(&C[(size_t)(row + 8) * 1024 + col]) = v1;
        }
    }
}

// ---------------- scan: h_t = lam*h_{t-1} + u_t, chunked (fp32) ---------------
// K1: chunk aggregates only -> g_v. 2 u's per thread (float2).
__global__ void scan_agg_kernel(const float* __restrict__ plog)
{
    const int g  = blockIdx.x * 256 + threadIdx.x;   // B*NC*U/2 threads
    const int u2 = g & (U_ / 2 - 1);                 // float2 index in u
    const int c  = (g >> 9) & (NC - 1);
    const int b  = g >> 15;
    const int uu = u2 * 2;
    const float lam0 = expf(-expf(plog[uu]));
    const float lam1 = expf(-expf(plog[uu + 1]));
    const float2* p = reinterpret_cast<const float2*>(
        g_u + (size_t)(b * L_ + c * CL) * U_) + u2;
    float h0 = 0.f, h1 = 0.f;
    #pragma unroll 8
    for (int t = 0; t < CL; t++) {
        float2 v = p[(size_t)t * (U_ / 2)];
        h0 = fmaf(lam0, h0, v.x);
        h1 = fmaf(lam1, h1, v.y);
    }
    reinterpret_cast<float2*>(g_v + (size_t)(b * NC + c) * U_)[u2] =
        make_float2(h0, h1);
}

// K2: exclusive scan of chunk aggregates along the chunk axis.
// One warp per (b,u): pair-combine + Kogge-Stone shfl scan (ratio lamC^2).
__global__ void scan_carry_kernel(const float* __restrict__ plog)
{
    const int idx  = blockIdx.x * 256 + threadIdx.x;  // B*U warps total
    const int lane = idx & 31;
    const int w    = idx >> 5;          // 0 .. B_*U_-1
    const int uu   = w & (U_ - 1);
    const int b    = w >> 10;
    const float nu   = expf(plog[uu]);
    const float lamC = expf(-(float)CL * nu);
    float* pv = g_v + (size_t)b * NC * U_ + uu;

    // lane holds chunks 2*lane, 2*lane+1
    const float a0 = pv[(size_t)(2 * lane) * U_];
    const float a1 = pv[(size_t)(2 * lane + 1) * U_];
    float p = fmaf(lamC, a0, a1);        // pair aggregate
    const float lamC2 = lamC * lamC;

    // inclusive warp scan of p with geometric ratio lamC2
    float mult = lamC2;
    #pragma unroll
    for (int s = 1; s < 32; s <<= 1) {
        float other = __shfl_up_sync(0xffffffffu, p, s);
        if (lane >= s) p = fmaf(mult, other, p);
        mult = mult * mult;
    }

    const float Pprev = __shfl_up_sync(0xffffffffu, p, 1);
    const float E0 = (lane == 0) ? 0.f : Pprev;   // state before chunk 2*lane
    const float E1 = fmaf(lamC, E0, a0);          // state before chunk 2*lane+1
    pv[(size_t)(2 * lane) * U_]     = E0;
    pv[(size_t)(2 * lane + 1) * U_] = E1;
}

// K3: redo local scan seeded with carry, * gamma, emit fp16 for GEMM2.
// 2 u's per thread (float2 in, half2 out).
__global__ void scan_apply_kernel(const float* __restrict__ plog)
{
    const int g  = blockIdx.x * 256 + threadIdx.x;   // B*NC*U/2 threads
    const int u2 = g & (U_ / 2 - 1);
    const int c  = (g >> 9) & (NC - 1);
    const int b  = g >> 15;
    const int uu = u2 * 2;
    const float lam0 = expf(-expf(plog[uu]));
    const float lam1 = expf(-expf(plog[uu + 1]));
    const float gam0 = expf(plog[U_ + uu]);
    const float gam1 = expf(plog[U_ + uu + 1]);
    float2 h = reinterpret_cast<const float2*>(
        g_v + (size_t)(b * NC + c) * U_)[u2];        // state before chunk
    const float2* p = reinterpret_cast<const float2*>(
        g_u + (size_t)(b * L_ + c * CL) * U_) + u2;
    __half2* q = reinterpret_cast<__half2*>(
        g_uh + (size_t)(b * L_ + c * CL) * U_) + u2;
    #pragma unroll 8
    for (int t = 0; t < CL; t++) {
        float2 v = p[(size_t)t * (U_ / 2)];
        h.x = fmaf(lam0, h.x, v.x);
        h.y = fmaf(lam1, h.y, v.y);
        q[(size_t)t * (U_ / 2)] = __floats2half2_rn(h.x * gam0, h.y * gam1);
    }
}

// ---------------- launch ------------------------------------------------------
extern "C" void kernel_launch(void* const* d_in, const int* in_sizes, int n_in,
                              void* d_out, int out_size)
{
    const float* inputs = (const float*)d_in[0];
    const float* Wi     = (const float*)d_in[1];
    const float* bi     = (const float*)d_in[2];
    const float* Wo     = (const float*)d_in[3];
    const float* bo     = (const float*)d_in[4];
    const float* plog   = (const float*)d_in[5];
    float* out = (float*)d_out;

    cudaFuncSetAttribute(gemm_f16_kernel,
                         cudaFuncAttributeMaxDynamicSharedMemorySize,
                         GEMM_SMEM);

    // fp16 conversion: inputs + both weights in one launch
    cvt_all_kernel<<<2048, 256>>>((const float4*)inputs,
                                  (const float4*)Wi,
                                  (const float4*)Wo);

    // GEMM1: u = inputs * Wi^T + bi   -> g_u (fp32)
    gemm_f16_kernel<<<dim3(U_ / TN, M_ / TM), 256, GEMM_SMEM>>>(0, bi, nullptr);

    // scan (chunked linear recurrence) + gamma -> g_uh (fp16)
    scan_agg_kernel<<<(B_ * NC * U_ / 2) / 256, 256>>>(plog);
    scan_carry_kernel<<<(B_ * U_ * 32) / 256, 256>>>(plog);
    scan_apply_kernel<<<(B_ * NC * U_ / 2) / 256, 256>>>(plog);

    // GEMM2: out = x * Wo^T + bo
    gemm_f16_kernel<<<dim3(H_ / TN, M_ / TM), 256, GEMM_SMEM>>>(1, bo, out);
}

// round 10
// speedup vs baseline: 1.5460x; 1.0812x over previous
#include <cuda_runtime.h>
#include <cuda_fp16.h>
#include <cstdint>

// Problem constants
#define B_  4
#define L_  4096
#define H_  1024
#define U_  1024
#define M_  (B_*L_)          // 16384 rows

constexpr int CL = 64;            // scan chunk length
constexpr int NC = L_ / CL;       // 64 chunks per sequence

// ---------------- scratch (device globals; no allocation allowed) -------------
__device__ __half g_inH[(size_t)M_ * H_];   // fp16 inputs          (32 MB)
__device__ __half g_WiH[(size_t)U_ * H_];   // fp16 Wi              (2 MB)
__device__ __half g_WoH[(size_t)H_ * U_];   // fp16 Wo              (2 MB)
__device__ __half g_uh [(size_t)M_ * U_];   // fp16 u, then scanned x (32 MB)
__device__ float  g_v  [(size_t)B_ * NC * U_]; // chunk carries      (1 MB)

// ---------------- helpers ----------------------------------------------------
__device__ __forceinline__ uint32_t smem_u32(const void* p) {
    uint32_t a;
    asm("{ .reg .u64 t; cvta.to.shared.u64 t, %1; cvt.u32.u64 %0, t; }"
        : "=r"(a) : "l"(p));
    return a;
}

__device__ __forceinline__ void cp16(uint32_t saddr, const void* g) {
    asm volatile("cp.async.cg.shared.global [%0], [%1], 16;" :: "r"(saddr), "l"(g));
}
__device__ __forceinline__ void cp_commit() {
    asm volatile("cp.async.commit_group;" ::: "memory");
}

// ldmatrix x4: 4 matrices of 8 rows x 16B (8 halves).
__device__ __forceinline__ void ldsm4(uint32_t* r, uint32_t addr) {
    asm volatile("ldmatrix.sync.aligned.m8n8.x4.shared.b16 {%0,%1,%2,%3}, [%4];"
                 : "=r"(r[0]), "=r"(r[1]), "=r"(r[2]), "=r"(r[3]) : "r"(addr));
}

__device__ __forceinline__ void mma_f16(float* d, const uint32_t* a, const uint32_t* b) {
    asm volatile(
        "mma.sync.aligned.m16n8k16.row.col.f32.f16.f16.f32 "
        "{%0,%1,%2,%3}, {%4,%5,%6,%7}, {%8,%9}, {%0,%1,%2,%3};\n"
        : "+f"(d[0]), "+f"(d[1]), "+f"(d[2]), "+f"(d[3])
        : "r"(a[0]), "r"(a[1]), "r"(a[2]), "r"(a[3]),
          "r"(b[0]), "r"(b[1]));
}

// ---------------- fused fp16 conversion (inputs + Wi + Wo) --------------------
__global__ void cvt_all_kernel(const float4* __restrict__ in,
                               const float4* __restrict__ wi,
                               const float4* __restrict__ wo)
{
    const size_t n_in = (size_t)M_ * H_ / 8;    // uint4 (8-half) chunks
    const size_t n_w  = (size_t)U_ * H_ / 8;
    const size_t n_tot = n_in + 2 * n_w;
    size_t i = (size_t)blockIdx.x * blockDim.x + threadIdx.x;
    const size_t stride = (size_t)gridDim.x * blockDim.x;
    for (; i < n_tot; i += stride) {
        const float4* src;
        __half* dst;
        size_t j;
        if (i < n_in)            { src = in; dst = g_inH; j = i; }
        else if (i < n_in + n_w) { src = wi; dst = g_WiH; j = i - n_in; }
        else                     { src = wo; dst = g_WoH; j = i - n_in - n_w; }
        float4 a = src[2 * j], b = src[2 * j + 1];
        __half2 h[4];
        h[0] = __floats2half2_rn(a.x, a.y);
        h[1] = __floats2half2_rn(a.z, a.w);
        h[2] = __floats2half2_rn(b.x, b.y);
        h[3] = __floats2half2_rn(b.z, b.w);
        reinterpret_cast<uint4*>(dst)[j] = *reinterpret_cast<uint4*>(h);
    }
}

// ---------------- FP16 mma GEMM: C = A*B^T + bias ----------------------------
// CTA 128x128, 8 warps (4M x 2N), warp tile 32x64, BK=64 halves (=128B rows),
// 3-stage cp.async, mma m16n8k16, fp32 accum. 2 CTAs/SM.
// sel==0: A=g_inH, B=g_WiH, C=g_uh (fp16).  sel==1: A=g_uh, B=g_WoH, C=out(fp32).
constexpr int TM = 128, TN = 128, BKH = 64;   // BKH in halves
constexpr int KDIM = 1024;                    // halves
constexpr int NKT  = KDIM / BKH;              // 16 chunks
constexpr int NSTAGE = 3;
constexpr int STAGE_A   = TM * 128;           // 16384 B per operand tile
constexpr int STAGE_TOT = 2 * STAGE_A;        // 32768 B
constexpr int GEMM_SMEM = NSTAGE * STAGE_TOT; // 98304 B

__global__ __launch_bounds__(256, 2)
void gemm_f16_kernel(int sel, const float* __restrict__ bias, float* __restrict__ Cext)
{
    extern __shared__ char smem[];
    const uint32_t sb = smem_u32(smem);
    const int tid = threadIdx.x;
    const int warp = tid >> 5, lane = tid & 31;

    const __half* __restrict__ A  = sel ? g_uh  : g_inH;
    const __half* __restrict__ Bw = sel ? g_WoH : g_WiH;
    const int bm = blockIdx.y * TM;
    const int bn = blockIdx.x * TN;

    const int wm = (warp >> 1) * 32;      // warp M offset
    const int wn = (warp & 1) * 64;       // warp N offset

    // ---- staging: thread -> (row, 16B-chunk group); rows are 128B ----
    const int srow = tid >> 1;            // 0..127
    const int gb0  = (tid & 1) * 4;       // chunk base 0 or 4
    uint32_t swoff[4];
    #pragma unroll
    for (int i = 0; i < 4; i++)
        swoff[i] = (uint32_t)srow * 128u + ((uint32_t)((gb0 + i) ^ (srow & 7)) << 4);
    const __half* Arow = A  + (size_t)(bm + srow) * KDIM;
    const __half* Brow = Bw + (size_t)(bn + srow) * KDIM;

    // ---- ldmatrix per-lane invariants (A x4 and B x4, non-trans) ----
    const int lrA  = lane & 15;           // A row-in-16
    const int gsA  = lane >> 4;           // A k-chunk select (0/1)
    const int lrB  = ((lane & 16) >> 1) + (lane & 7);   // B row offset 0..15
    const int gsB  = (lane >> 3) & 1;     // B k-chunk select

    float acc[2][8][4];
    #pragma unroll
    for (int mt = 0; mt < 2; mt++)
        #pragma unroll
        for (int nt = 0; nt < 8; nt++)
            #pragma unroll
            for (int i = 0; i < 4; i++) acc[mt][nt][i] = 0.f;

    // ---- prologue: stage chunks 0,1 ----
    #pragma unroll
    for (int c = 0; c < NSTAGE - 1; c++) {
        const uint32_t ao = sb + c * STAGE_TOT;
        #pragma unroll
        for (int i = 0; i < 4; i++) {
            cp16(ao + swoff[i], Arow + c * BKH + (gb0 + i) * 8);
            cp16(ao + STAGE_A + swoff[i], Brow + c * BKH + (gb0 + i) * 8);
        }
        cp_commit();
    }

    #pragma unroll 1
    for (int kt = 0; kt < NKT; kt++) {
        asm volatile("cp.async.wait_group 1;" ::: "memory");
        __syncthreads();

        if (kt + 2 < NKT) {
            const uint32_t ao = sb + ((kt + 2) % NSTAGE) * STAGE_TOT;
            const int k0 = (kt + 2) * BKH;
            #pragma unroll
            for (int i = 0; i < 4; i++) {
                cp16(ao + swoff[i], Arow + k0 + (gb0 + i) * 8);
                cp16(ao + STAGE_A + swoff[i], Brow + k0 + (gb0 + i) * 8);
            }
        }
        cp_commit();

        const uint32_t sA = sb + (kt % NSTAGE) * STAGE_TOT;
        const uint32_t sB = sA + STAGE_A;

        #pragma unroll
        for (int ks = 0; ks < 4; ks++) {          // 4 x k16 per 64-half chunk
            uint32_t afr[2][4], bfr[4][4];
            #pragma unroll
            for (int mt = 0; mt < 2; mt++) {
                const int r = wm + mt * 16 + lrA;
                const uint32_t g = (uint32_t)((ks * 2 + gsA) ^ (lrA & 7));
                ldsm4(afr[mt], sA + (uint32_t)r * 128u + (g << 4));
            }
            #pragma unroll
            for (int p = 0; p < 4; p++) {
                const int r = wn + p * 16 + lrB;
                const uint32_t g = (uint32_t)((ks * 2 + gsB) ^ (lrB & 7));
                ldsm4(bfr[p], sB + (uint32_t)r * 128u + (g << 4));
            }
            #pragma unroll
            for (int mt = 0; mt < 2; mt++)
                #pragma unroll
                for (int nt = 0; nt < 8; nt++)
                    mma_f16(acc[mt][nt], afr[mt], &bfr[nt >> 1][(nt & 1) * 2]);
        }
    }

    // ---- epilogue: add bias; write fp16 (sel=0 -> g_uh) or fp32 (sel=1) ----
    const int gid = lane >> 2, t4 = lane & 3;
    if (sel == 0) {
        #pragma unroll
        for (int mt = 0; mt < 2; mt++) {
            const int row = bm + wm + mt * 16 + gid;
            #pragma unroll
            for (int nt = 0; nt < 8; nt++) {
                const int col = bn + wn + nt * 8 + t4 * 2;
                const float b0 = bias[col], b1 = bias[col + 1];
                __half2 v0 = __floats2half2_rn(acc[mt][nt][0] + b0, acc[mt][nt][1] + b1);
                __half2 v1 = __floats2half2_rn(acc[mt][nt][2] + b0, acc[mt][nt][3] + b1);
                *reinterpret_cast<__half2*>(&g_uh[(size_t)row * 1024 + col]) = v0;
                *reinterpret_cast<__half2*>(&g_uh[(size_t)(row + 8) * 1024 + col]) = v1;
            }
        }
    } else {
        #pragma unroll
        for (int mt = 0; mt < 2; mt++) {
            const int row = bm + wm + mt * 16 + gid;
            #pragma unroll
            for (int nt = 0; nt < 8; nt++) {
                const int col = bn + wn + nt * 8 + t4 * 2;
                const float b0 = bias[col], b1 = bias[col + 1];
                float2 v0 = make_float2(acc[mt][nt][0] + b0, acc[mt][nt][1] + b1);
                float2 v1 = make_float2(acc[mt][nt][2] + b0, acc[mt][nt][3] + b1);
                *reinterpret_cast<float2*>(&Cext[(size_t)row * 1024 + col]) = v0;
                *reinterpret_cast<float2*>(&Cext[(size_t)(row + 8) * 1024 + col]) = v1;
            }
        }
    }
}

// ---------------- scan: h_t = lam*h_{t-1} + u_t (fp32 math, fp16 storage) -----
// K1: chunk aggregates only -> g_v. 2 u's per thread (half2 in).
__global__ void scan_agg_kernel(const float* __restrict__ plog)
{
    const int g  = blockIdx.x * 256 + threadIdx.x;   // B*NC*U/2 threads
    const int u2 = g & (U_ / 2 - 1);                 // half2 index in u
    const int c  = (g >> 9) & (NC - 1);
    const int b  = g >> 15;
    const int uu = u2 * 2;
    const float lam0 = expf(-expf(plog[uu]));
    const float lam1 = expf(-expf(plog[uu + 1]));
    const __half2* p = reinterpret_cast<const __half2*>(
        g_uh + (size_t)(b * L_ + c * CL) * U_) + u2;
    float h0 = 0.f, h1 = 0.f;
    #pragma unroll 8
    for (int t = 0; t < CL; t++) {
        float2 v = __half22float2(p[(size_t)t * (U_ / 2)]);
        h0 = fmaf(lam0, h0, v.x);
        h1 = fmaf(lam1, h1, v.y);
    }
    reinterpret_cast<float2*>(g_v + (size_t)(b * NC + c) * U_)[u2] =
        make_float2(h0, h1);
}

// K2: exclusive scan of chunk aggregates along the chunk axis.
// One warp per (b,u): pair-combine + Kogge-Stone shfl scan (ratio lamC^2).
__global__ void scan_carry_kernel(const float* __restrict__ plog)
{
    const int idx  = blockIdx.x * 256 + threadIdx.x;  // B*U warps total
    const int lane = idx & 31;
    const int w    = idx >> 5;          // 0 .. B_*U_-1
    const int uu   = w & (U_ - 1);
    const int b    = w >> 10;
    const float nu   = expf(plog[uu]);
    const float lamC = expf(-(float)CL * nu);
    float* pv = g_v + (size_t)b * NC * U_ + uu;

    // lane holds chunks 2*lane, 2*lane+1
    const float a0 = pv[(size_t)(2 * lane) * U_];
    const float a1 = pv[(size_t)(2 * lane + 1) * U_];
    float p = fmaf(lamC, a0, a1);        // pair aggregate
    const float lamC2 = lamC * lamC;

    // inclusive warp scan of p with geometric ratio lamC2
    float mult = lamC2;
    #pragma unroll
    for (int s = 1; s < 32; s <<= 1) {
        float other = __shfl_up_sync(0xffffffffu, p, s);
        if (lane >= s) p = fmaf(mult, other, p);
        mult = mult * mult;
    }

    const float Pprev = __shfl_up_sync(0xffffffffu, p, 1);
    const float E0 = (lane == 0) ? 0.f : Pprev;   // state before chunk 2*lane
    const float E1 = fmaf(lamC, E0, a0);          // state before chunk 2*lane+1
    pv[(size_t)(2 * lane) * U_]     = E0;
    pv[(size_t)(2 * lane + 1) * U_] = E1;
}

// K3: redo local scan seeded with carry, * gamma, rewrite g_uh in place (fp16).
__global__ void scan_apply_kernel(const float* __restrict__ plog)
{
    const int g  = blockIdx.x * 256 + threadIdx.x;   // B*NC*U/2 threads
    const int u2 = g & (U_ / 2 - 1);
    const int c  = (g >> 9) & (NC - 1);
    const int b  = g >> 15;
    const int uu = u2 * 2;
    const float lam0 = expf(-expf(plog[uu]));
    const float lam1 = expf(-expf(plog[uu + 1]));
    const float gam0 = expf(plog[U_ + uu]);
    const float gam1 = expf(plog[U_ + uu + 1]);
    float2 h = reinterpret_cast<const float2*>(
        g_v + (size_t)(b * NC + c) * U_)[u2];        // state before chunk
    __half2* p = reinterpret_cast<__half2*>(
        g_uh + (size_t)(b * L_ + c * CL) * U_) + u2;
    #pragma unroll 8
    for (int t = 0; t < CL; t++) {
        float2 v = __half22float2(p[(size_t)t * (U_ / 2)]);
        h.x = fmaf(lam0, h.x, v.x);
        h.y = fmaf(lam1, h.y, v.y);
        p[(size_t)t * (U_ / 2)] = __floats2half2_rn(h.x * gam0, h.y * gam1);
    }
}

// ---------------- launch ------------------------------------------------------
extern "C" void kernel_launch(void* const* d_in, const int* in_sizes, int n_in,
                              void* d_out, int out_size)
{
    const float* inputs = (const float*)d_in[0];
    const float* Wi     = (const float*)d_in[1];
    const float* bi     = (const float*)d_in[2];
    const float* Wo     = (const float*)d_in[3];
    const float* bo     = (const float*)d_in[4];
    const float* plog   = (const float*)d_in[5];
    float* out = (float*)d_out;

    cudaFuncSetAttribute(gemm_f16_kernel,
                         cudaFuncAttributeMaxDynamicSharedMemorySize,
                         GEMM_SMEM);

    // fp16 conversion: inputs + both weights in one launch
    cvt_all_kernel<<<2048, 256>>>((const float4*)inputs,
                                  (const float4*)Wi,
                                  (const float4*)Wo);

    // GEMM1: u = inputs * Wi^T + bi   -> g_uh (fp16)
    gemm_f16_kernel<<<dim3(U_ / TN, M_ / TM), 256, GEMM_SMEM>>>(0, bi, nullptr);

    // scan (chunked linear recurrence) + gamma, in place on g_uh
    scan_agg_kernel<<<(B_ * NC * U_ / 2) / 256, 256>>>(plog);
    scan_carry_kernel<<<(B_ * U_ * 32) / 256, 256>>>(plog);
    scan_apply_kernel<<<(B_ * NC * U_ / 2) / 256, 256>>>(plog);

    // GEMM2: out = x * Wo^T + bo
    gemm_f16_kernel<<<dim3(H_ / TN, M_ / TM), 256, GEMM_SMEM>>>(1, bo, out);
}